// round 14
// baseline (speedup 1.0000x reference)
#include <cuda_runtime.h>
#include <cuda_bf16.h>
#include <cstdint>
#include <math.h>

#define VOCAB  32000
#define HIDDEN 256
#define BATCH  32
#define SEQ    128
#define NPOS   (BATCH * SEQ)                  // 4096
#define PROBS_ELEMS ((size_t)NPOS * VOCAB)    // 131,072,000
#define KEXT   768                            // [h_hi | h_lo | h_hi] x [e_hi | e_hi | e_lo]
#define NT2    125                            // 256-wide n-tiles
#define MT2    32                             // 128-row m-tiles

// ---- device scratch ----
__device__ float g_A[NPOS * HIDDEN];
__device__ float g_h1[NPOS * HIDDEN];
__device__ float g_WT[4 * HIDDEN * HIDDEN];
__device__ __nv_bfloat16 g_Aext[(size_t)NPOS * KEXT];    // 6 MB
__device__ __nv_bfloat16 g_Bext[(size_t)VOCAB * KEXT];   // 49 MB
__device__ float g_pmax[(size_t)NPOS * 512];             // [row][ntile*4+wn]
__device__ float g_psum[(size_t)NPOS * 512];
__device__ float g_rowM[NPOS];
__device__ float g_rowInv[NPOS];

// =========================== PTX helpers (sm_90 baseline) ==================
__device__ __forceinline__ uint32_t smem_to_u32(const void* p) {
    uint32_t a;
    asm("{ .reg .u64 t; cvta.to.shared.u64 t, %1; cvt.u32.u64 %0, t; }" : "=r"(a) : "l"(p));
    return a;
}
#define SMEM_SWIZZLE_128B(off) ((off) ^ (((off) >> 3) & 0x70))

__device__ __forceinline__ void cp_async16(uint32_t dst, const void* src) {
    asm volatile("cp.async.cg.shared.global [%0], [%1], 16;" :: "r"(dst), "l"(src) : "memory");
}
#define CP_COMMIT() asm volatile("cp.async.commit_group;" ::: "memory")
#define CP_WAIT0()  asm volatile("cp.async.wait_group 0;" ::: "memory")

__device__ __forceinline__ void ldm_x4(uint32_t& r0, uint32_t& r1, uint32_t& r2, uint32_t& r3,
                                       uint32_t addr) {
    asm volatile("ldmatrix.sync.aligned.m8n8.x4.shared.b16 {%0,%1,%2,%3}, [%4];"
                 : "=r"(r0), "=r"(r1), "=r"(r2), "=r"(r3) : "r"(addr));
}
__device__ __forceinline__ void mma16816(float* c, const uint32_t* a, uint32_t b0, uint32_t b1) {
    asm volatile("mma.sync.aligned.m16n8k16.row.col.f32.bf16.bf16.f32 "
                 "{%0,%1,%2,%3}, {%4,%5,%6,%7}, {%8,%9}, {%0,%1,%2,%3};"
                 : "+f"(c[0]), "+f"(c[1]), "+f"(c[2]), "+f"(c[3])
                 : "r"(a[0]), "r"(a[1]), "r"(a[2]), "r"(a[3]), "r"(b0), "r"(b1));
}

// cluster helpers
__device__ __forceinline__ uint32_t mapa_u32(uint32_t addr, uint32_t rank) {
    uint32_t r;
    asm("mapa.shared::cluster.u32 %0, %1, %2;" : "=r"(r) : "r"(addr), "r"(rank));
    return r;
}
__device__ __forceinline__ void st_cluster_f32(uint32_t addr, float v) {
    asm volatile("st.shared::cluster.f32 [%0], %1;" :: "r"(addr), "f"(v) : "memory");
}
__device__ __forceinline__ void mbar_arrive_rel_cluster(uint32_t remote_mb) {
    asm volatile("mbarrier.arrive.release.cluster.shared::cluster.b64 _, [%0];"
                 :: "r"(remote_mb) : "memory");
}
#define MBARRIER_INIT(mb, cnt) \
    asm volatile("mbarrier.init.shared.b64 [%0], %1;" :: "r"((uint32_t)(mb)), "r"((uint32_t)(cnt)) : "memory")
#define CLUSTER_SYNC() do { \
    asm volatile("barrier.cluster.arrive.aligned;" ::: "memory"); \
    asm volatile("barrier.cluster.wait.aligned;" ::: "memory"); \
} while (0)
#define MBAR_WAIT_PARITY_CLUSTER(mb, par) do { \
    uint32_t _mb = (mb), _par = (par), _done; \
    asm volatile("{ .reg .pred p; mbarrier.try_wait.parity.acquire.cluster.shared::cta.b64 p, [%1], %2; selp.b32 %0, 1, 0, p; }" \
        : "=r"(_done) : "r"(_mb), "r"(_par) : "memory"); \
    if (!_done) { \
        asm volatile("{ .reg .pred P1; WL_%=: mbarrier.try_wait.parity.acquire.cluster.shared::cta.b64 P1, [%0], %1, 0x989680; @P1 bra.uni WD_%=; bra.uni WL_%=; WD_%=: }" \
            :: "r"(_mb), "r"(_par) : "memory"); \
    } \
} while (0)

// =========================== prep: W transposes + emb split ================
__global__ void prep(const float* __restrict__ Wx1, const float* __restrict__ Wh1,
                     const float* __restrict__ Wx2, const float* __restrict__ Wh2,
                     const float* __restrict__ emb)
{
    __shared__ float tile[32][33];
    int blk = blockIdx.x;
    if (blk < 256) {
        int z = blk >> 6, rem = blk & 63, bx = rem & 7, by = rem >> 3;
        const float* src = (z == 0) ? Wx1 : (z == 1) ? Wh1 : (z == 2) ? Wx2 : Wh2;
        float* dst = g_WT + (size_t)z * HIDDEN * HIDDEN;
        int x0 = bx * 32, y0 = by * 32;
        int tx = threadIdx.x & 31, ty = threadIdx.x >> 5;
        for (int dy = ty; dy < 32; dy += 8)
            tile[dy][tx] = src[(y0 + dy) * HIDDEN + x0 + tx];
        __syncthreads();
        for (int dy = ty; dy < 32; dy += 8)
            dst[(x0 + dy) * HIDDEN + y0 + tx] = tile[tx][dy];
    } else {
        for (size_t i = (size_t)(blk - 256) * 256 + threadIdx.x;
             i < (size_t)VOCAB * HIDDEN; i += (size_t)8192 * 256) {
            float x = emb[i];
            __nv_bfloat16 hi = __float2bfloat16(x);
            __nv_bfloat16 lo = __float2bfloat16(x - __bfloat162float(hi));
            size_t row = i >> 8; int k = (int)(i & 255);
            __nv_bfloat16* B = g_Bext + row * KEXT;
            B[k] = hi; B[256 + k] = hi; B[512 + k] = lo;
        }
    }
}

// g_A[n,j] = bias[j] + sum_k X[n,k] * WxT[k,j]   (16 rows per CTA)
__global__ void pre_gemm(const float* __restrict__ emb, const int* __restrict__ tokens,
                         const int* __restrict__ lengths, const float* __restrict__ bias,
                         int layer)
{
    __shared__ float xs[16][HIDDEN];
    const float* WT = g_WT + (size_t)(layer == 0 ? 0 : 2) * HIDDEN * HIDDEN;
    int n0  = blockIdx.x * 16;
    int tid = threadIdx.x;

    for (int r = 0; r < 16; r++) {
        int n = n0 + r;
        float v;
        if (layer == 0) {
            int b = n / SEQ, t = n % SEQ;
            v = (t < lengths[b]) ? emb[(size_t)tokens[n] * HIDDEN + tid] : 0.f;
        } else {
            v = g_h1[(size_t)n * HIDDEN + tid];
        }
        xs[r][tid] = v;
    }
    __syncthreads();

    float acc[16];
#pragma unroll
    for (int r = 0; r < 16; r++) acc[r] = 0.f;

    for (int k = 0; k < HIDDEN; k += 8) {
        float w[8];
#pragma unroll
        for (int kk = 0; kk < 8; kk++) w[kk] = WT[(k + kk) * HIDDEN + tid];
#pragma unroll
        for (int r = 0; r < 16; r++) {
            float4 x0 = *(const float4*)&xs[r][k];
            float4 x1 = *(const float4*)&xs[r][k + 4];
            acc[r] += x0.x * w[0] + x0.y * w[1] + x0.z * w[2] + x0.w * w[3]
                    + x1.x * w[4] + x1.y * w[5] + x1.z * w[6] + x1.w * w[7];
        }
    }
    float b = bias[tid];
#pragma unroll
    for (int r = 0; r < 16; r++)
        g_A[(size_t)(n0 + r) * HIDDEN + tid] = acc[r] + b;
}

// ===== recurrence: 2-CTA cluster, W_h in regs, DOUBLE-BUFFERED hs ==========
__global__ void __cluster_dims__(2, 1, 1) __launch_bounds__(512, 1)
rnn2db(const int* __restrict__ lengths, float* __restrict__ hout, int layer)
{
    __shared__ float hs[2][HIDDEN];
    __shared__ float red[4][128];
    __shared__ alignas(8) uint64_t mbar;

    const float* WhT = g_WT + (size_t)(layer * 2 + 1) * HIDDEN * HIDDEN;
    float* out = hout ? hout : g_h1;
    bool dosplit = (hout != nullptr);

    int tid = threadIdx.x;
    int jo  = tid & 127, kq = tid >> 7, k0 = kq * 64;
    int b   = blockIdx.x >> 1;
    int r   = blockIdx.x & 1;
    int j   = r * 128 + jo;
    int len = lengths[b];

    float w[64];
#pragma unroll
    for (int kk = 0; kk < 64; kk++) w[kk] = WhT[(k0 + kk) * HIDDEN + j];

    uint32_t mb_local = smem_to_u32(&mbar);
    uint32_t hs_local = smem_to_u32(&hs[0][0]);
    uint32_t mb_peer  = mapa_u32(mb_local, r ^ 1);
    uint32_t hs_peer  = mapa_u32(hs_local, r ^ 1);

    if (tid < HIDDEN) hs[0][tid] = 0.f;
    if (tid == 0) MBARRIER_INIT(mb_local, 128);
    __syncthreads();
    CLUSTER_SYNC();

    int ph = 0;
    const float* Arow = g_A + (size_t)b * SEQ * HIDDEN + j;
    for (int t = 0; t < len; t++) {
        int rb = t & 1, wb = rb ^ 1;
        float av = 0.f;
        if (tid < 128) av = Arow[(size_t)t * HIDDEN];

        float a0 = 0.f, a1 = 0.f, a2 = 0.f, a3 = 0.f;
#pragma unroll
        for (int kk = 0; kk < 64; kk += 4) {
            float4 h4 = *(const float4*)&hs[rb][k0 + kk];
            a0 += h4.x * w[kk];
            a1 += h4.y * w[kk + 1];
            a2 += h4.z * w[kk + 2];
            a3 += h4.w * w[kk + 3];
        }
        red[kq][jo] = (a0 + a1) + (a2 + a3);
        __syncthreads();               // ALL reads of hs[rb] complete; red ready

        if (tid < 128) {
            float v = red[0][jo] + red[1][jo] + red[2][jo] + red[3][jo] + av;
            float h = tanhf(v);
            hs[wb][j] = h;
            st_cluster_f32(hs_peer + (uint32_t)(wb * HIDDEN + j) * 4u, h);
            out[((size_t)b * SEQ + t) * HIDDEN + j] = h;
            if (dosplit) {
                __nv_bfloat16 hi = __float2bfloat16(h);
                __nv_bfloat16 lo = __float2bfloat16(h - __bfloat162float(hi));
                __nv_bfloat16* A = g_Aext + ((size_t)b * SEQ + t) * KEXT;
                A[j] = hi; A[256 + j] = lo; A[512 + j] = hi;
            }
            mbar_arrive_rel_cluster(mb_peer);
        }
        __syncthreads();               // local hs[wb] visible; red reusable
        MBAR_WAIT_PARITY_CLUSTER(mb_local, ph);
        ph ^= 1;
    }
    for (int t = len; t < SEQ; t++)
        if (tid < 128) {
            out[((size_t)b * SEQ + t) * HIDDEN + j] = 0.f;
            if (dosplit) {
                __nv_bfloat16 z = __float2bfloat16(0.f);
                __nv_bfloat16* A = g_Aext + ((size_t)b * SEQ + t) * KEXT;
                A[j] = z; A[256 + j] = z; A[512 + j] = z;
            }
        }
    CLUSTER_SYNC();
}

// ==================== mma.sync projection + partial softmax ================
// CTA tile 128(m) x 256(n), 256 threads, 8 warps in 2(m) x 4(n), warp tile
// 64x64 (128 accum regs) -> per-output smem traffic drops 35% vs 64x32.
// grid (32 m-tiles x [fastest], 125 n-tiles y). K = 768 (12 chunks of 64).
// SMEM: A0 @0 (16K) A1 @16384 | B0 @32768 (32K) B1 @65536; total 98304 B.
#define MMA_SMEM_BYTES 98304
__global__ void __launch_bounds__(256, 1) mma_out(float* __restrict__ probs)
{
    extern __shared__ char smem[];
    uint32_t sb = smem_to_u32(smem);
    const uint32_t stA[2] = {0u, 16384u};
    const uint32_t stB[2] = {32768u, 65536u};
    int tid = threadIdx.x, wid = tid >> 5, lane = tid & 31;
    int wm = wid >> 2, wn = wid & 3;          // 2(m) x 4(n), warp tile 64x64
    int m0 = blockIdx.x * 128, n0 = blockIdx.y * 256;
    int ntile = blockIdx.y;

    const char* Agm = (const char*)g_Aext;    // row stride 1536 B
    const char* Bgm = (const char*)g_Bext;

    float c4[4][8][4];
#pragma unroll
    for (int i = 0; i < 4; i++)
#pragma unroll
        for (int jx = 0; jx < 8; jx++)
#pragma unroll
            for (int q = 0; q < 4; q++) c4[i][jx][q] = 0.f;

#define STAGE_COPY(s, buf) do {                                                    \
        int _kb = (s) * 128;                                                       \
        _Pragma("unroll")                                                          \
        for (int _i = 0; _i < 4; _i++) {       /* A: 128 rows x 8 groups */        \
            int _idx = tid + _i * 256;                                             \
            int _row = _idx >> 3, _g = _idx & 7;                                   \
            uint32_t _sw = SMEM_SWIZZLE_128B((uint32_t)(_row * 128 + _g * 16));    \
            cp_async16(sb + stA[buf] + _sw,                                        \
                       Agm + (size_t)(m0 + _row) * 1536 + _kb + _g * 16);          \
        }                                                                          \
        _Pragma("unroll")                                                          \
        for (int _i = 0; _i < 8; _i++) {       /* B: 256 rows x 8 groups */        \
            int _idx = tid + _i * 256;                                             \
            int _row = _idx >> 3, _g = _idx & 7;                                   \
            uint32_t _sw = SMEM_SWIZZLE_128B((uint32_t)(_row * 128 + _g * 16));    \
            cp_async16(sb + stB[buf] + _sw,                                        \
                       Bgm + (size_t)(n0 + _row) * 1536 + _kb + _g * 16);          \
        }                                                                          \
    } while (0)

    STAGE_COPY(0, 0);
    CP_COMMIT(); CP_WAIT0();
    __syncthreads();

    int sub = lane >> 3;
    for (int s = 0; s < 12; s++) {
        int buf = s & 1;
        if (s < 11) { STAGE_COPY(s + 1, buf ^ 1); CP_COMMIT(); }
        uint32_t abase = sb + stA[buf], bbase = sb + stB[buf];
#pragma unroll
        for (int kk = 0; kk < 4; kk++) {
            uint32_t a[4][4];
#pragma unroll
            for (int mi = 0; mi < 4; mi++) {
                int row = wm * 64 + mi * 16 + (lane & 7) + (sub & 1) * 8;
                int kb  = kk * 32 + (sub >> 1) * 16;
                ldm_x4(a[mi][0], a[mi][1], a[mi][2], a[mi][3],
                       abase + SMEM_SWIZZLE_128B((uint32_t)(row * 128 + kb)));
            }
#pragma unroll
            for (int np = 0; np < 4; np++) {
                uint32_t b0, b1, b2, b3;
                int nrow = wn * 64 + np * 16 + (lane & 7) + (sub >> 1) * 8;
                int kb   = kk * 32 + (sub & 1) * 16;
                ldm_x4(b0, b1, b2, b3,
                       bbase + SMEM_SWIZZLE_128B((uint32_t)(nrow * 128 + kb)));
#pragma unroll
                for (int mi = 0; mi < 4; mi++) {
                    mma16816(c4[mi][np * 2],     a[mi], b0, b1);
                    mma16816(c4[mi][np * 2 + 1], a[mi], b2, b3);
                }
            }
        }
        if (s < 11) CP_WAIT0();
        __syncthreads();
    }

    // epilogue: store logits, per-warp per-row (max,sumexp) partials -> gmem
    int gq = lane >> 2, tq = lane & 3;
#pragma unroll
    for (int mi = 0; mi < 4; mi++) {
#pragma unroll
        for (int h = 0; h < 2; h++) {
            int rloc = wm * 64 + mi * 16 + gq + h * 8;
            size_t grow = (size_t)(m0 + rloc);
            float m = -1e30f, ssum = 0.f;
#pragma unroll
            for (int ni = 0; ni < 8; ni++) {
                float v0 = c4[mi][ni][2 * h], v1 = c4[mi][ni][2 * h + 1];
                int col = n0 + wn * 64 + ni * 8 + 2 * tq;
                *(float2*)&probs[grow * VOCAB + col] = make_float2(v0, v1);
                float mn = fmaxf(m, fmaxf(v0, v1));
                ssum = ssum * __expf(m - mn) + __expf(v0 - mn) + __expf(v1 - mn);
                m = mn;
            }
#pragma unroll
            for (int o = 1; o <= 2; o <<= 1) {
                float mo = __shfl_xor_sync(0xffffffffu, m, o);
                float so = __shfl_xor_sync(0xffffffffu, ssum, o);
                float mn = fmaxf(m, mo);
                ssum = ssum * __expf(m - mn) + so * __expf(mo - mn);
                m = mn;
            }
            if (tq == 0) {
                g_pmax[grow * 512 + ntile * 4 + wn] = m;
                g_psum[grow * 512 + ntile * 4 + wn] = ssum;
            }
        }
    }
}

__global__ void combine_rows(const int* __restrict__ lengths)
{
    int row  = blockIdx.x * 8 + (threadIdx.x >> 5);
    int lane = threadIdx.x & 31;
    const float* pm = &g_pmax[(size_t)row * 512];
    const float* ps = &g_psum[(size_t)row * 512];
    float M = -1e30f, S = 0.f;
    for (int i = lane; i < NT2 * 4; i += 32) {
        float m = pm[i], s = ps[i];
        float mn = fmaxf(M, m);
        S = S * __expf(M - mn) + s * __expf(m - mn);
        M = mn;
    }
    for (int o = 16; o; o >>= 1) {
        float mo = __shfl_xor_sync(0xffffffffu, M, o);
        float so = __shfl_xor_sync(0xffffffffu, S, o);
        float mn = fmaxf(M, mo);
        S = S * __expf(M - mn) + so * __expf(mo - mn);
        M = mn;
    }
    if (lane == 0) {
        int b = row >> 7, t = row & 127;
        g_rowM[row]   = M;
        g_rowInv[row] = (t < lengths[b]) ? (1.f / S) : 0.f;
    }
}

__global__ void normalize_probs(float* __restrict__ probs)
{
    int row = blockIdx.x;
    float M = g_rowM[row], inv = g_rowInv[row];
    float4* p = (float4*)(probs + (size_t)row * VOCAB);
    for (int i = threadIdx.x; i < VOCAB / 4; i += 256) {
        float4 v = p[i];
        v.x = __expf(v.x - M) * inv;
        v.y = __expf(v.y - M) * inv;
        v.z = __expf(v.z - M) * inv;
        v.w = __expf(v.w - M) * inv;
        p[i] = v;
    }
}

// ---------------------------------------------------------------------------
extern "C" void kernel_launch(void* const* d_in, const int* in_sizes, int n_in,
                              void* d_out, int out_size)
{
    const int*   tokens  = (const int*)  d_in[0];
    const int*   lengths = (const int*)  d_in[1];
    const float* emb     = (const float*)d_in[2];
    const float* Wx1 = (const float*)d_in[3];
    const float* Wh1 = (const float*)d_in[4];
    const float* b1  = (const float*)d_in[5];
    const float* Wx2 = (const float*)d_in[6];
    const float* Wh2 = (const float*)d_in[7];
    const float* b2  = (const float*)d_in[8];

    float* probs = (float*)d_out;
    float* h2    = probs + PROBS_ELEMS;

    cudaFuncSetAttribute(mma_out, cudaFuncAttributeMaxDynamicSharedMemorySize,
                         MMA_SMEM_BYTES);

    prep    <<<8448, 256>>>(Wx1, Wh1, Wx2, Wh2, emb);
    pre_gemm<<<NPOS / 16, 256>>>(emb, tokens, lengths, b1, 0);
    rnn2db  <<<2 * BATCH, 512>>>(lengths, nullptr, 0);
    pre_gemm<<<NPOS / 16, 256>>>(emb, tokens, lengths, b2, 1);
    rnn2db  <<<2 * BATCH, 512>>>(lengths, h2, 1);                 // + bf16 split
    mma_out <<<dim3(MT2, NT2), 256, MMA_SMEM_BYTES>>>(probs);
    combine_rows<<<NPOS / 8, 256>>>(lengths);
    normalize_probs<<<NPOS, 256>>>(probs);
}

// round 16
// speedup vs baseline: 1.0734x; 1.0734x over previous
#include <cuda_runtime.h>
#include <cuda_bf16.h>
#include <cstdint>
#include <math.h>

#define VOCAB  32000
#define HIDDEN 256
#define BATCH  32
#define SEQ    128
#define NPOS   (BATCH * SEQ)                  // 4096
#define PROBS_ELEMS ((size_t)NPOS * VOCAB)    // 131,072,000
#define KEXT   768                            // [h_hi | h_lo | h_hi] x [e_hi | e_hi | e_lo]
#define NTILES (VOCAB / 128)                  // 250
#define MTILES (NPOS / 128)                   // 32

// ---- device scratch ----
__device__ float g_A[NPOS * HIDDEN];
__device__ float g_h1[NPOS * HIDDEN];
__device__ float g_WT[4 * HIDDEN * HIDDEN];
__device__ __nv_bfloat16 g_Aext[(size_t)NPOS * KEXT];    // 6 MB
__device__ __nv_bfloat16 g_Bext[(size_t)VOCAB * KEXT];   // 49 MB
__device__ float g_pmax[(size_t)NPOS * 256];             // [row][ntile]
__device__ float g_psum[(size_t)NPOS * 256];

// =========================== PTX helpers (sm_90 baseline) ==================
__device__ __forceinline__ uint32_t smem_to_u32(const void* p) {
    uint32_t a;
    asm("{ .reg .u64 t; cvta.to.shared.u64 t, %1; cvt.u32.u64 %0, t; }" : "=r"(a) : "l"(p));
    return a;
}
#define SMEM_SWIZZLE_128B(off) ((off) ^ (((off) >> 3) & 0x70))

__device__ __forceinline__ void cp_async16(uint32_t dst, const void* src) {
    asm volatile("cp.async.cg.shared.global [%0], [%1], 16;" :: "r"(dst), "l"(src) : "memory");
}
#define CP_COMMIT() asm volatile("cp.async.commit_group;" ::: "memory")
#define CP_WAIT0()  asm volatile("cp.async.wait_group 0;" ::: "memory")

__device__ __forceinline__ void ldm_x4(uint32_t& r0, uint32_t& r1, uint32_t& r2, uint32_t& r3,
                                       uint32_t addr) {
    asm volatile("ldmatrix.sync.aligned.m8n8.x4.shared.b16 {%0,%1,%2,%3}, [%4];"
                 : "=r"(r0), "=r"(r1), "=r"(r2), "=r"(r3) : "r"(addr));
}
__device__ __forceinline__ void mma16816(float* c, const uint32_t* a, uint32_t b0, uint32_t b1) {
    asm volatile("mma.sync.aligned.m16n8k16.row.col.f32.bf16.bf16.f32 "
                 "{%0,%1,%2,%3}, {%4,%5,%6,%7}, {%8,%9}, {%0,%1,%2,%3};"
                 : "+f"(c[0]), "+f"(c[1]), "+f"(c[2]), "+f"(c[3])
                 : "r"(a[0]), "r"(a[1]), "r"(a[2]), "r"(a[3]), "r"(b0), "r"(b1));
}

// cluster helpers
__device__ __forceinline__ uint32_t mapa_u32(uint32_t addr, uint32_t rank) {
    uint32_t r;
    asm("mapa.shared::cluster.u32 %0, %1, %2;" : "=r"(r) : "r"(addr), "r"(rank));
    return r;
}
__device__ __forceinline__ void st_cluster_f32(uint32_t addr, float v) {
    asm volatile("st.shared::cluster.f32 [%0], %1;" :: "r"(addr), "f"(v) : "memory");
}
__device__ __forceinline__ void mbar_arrive_rel_cluster(uint32_t remote_mb) {
    asm volatile("mbarrier.arrive.release.cluster.shared::cluster.b64 _, [%0];"
                 :: "r"(remote_mb) : "memory");
}
#define MBARRIER_INIT(mb, cnt) \
    asm volatile("mbarrier.init.shared.b64 [%0], %1;" :: "r"((uint32_t)(mb)), "r"((uint32_t)(cnt)) : "memory")
#define CLUSTER_SYNC() do { \
    asm volatile("barrier.cluster.arrive.aligned;" ::: "memory"); \
    asm volatile("barrier.cluster.wait.aligned;" ::: "memory"); \
} while (0)
#define MBAR_WAIT_PARITY_CLUSTER(mb, par) do { \
    uint32_t _mb = (mb), _par = (par), _done; \
    asm volatile("{ .reg .pred p; mbarrier.try_wait.parity.acquire.cluster.shared::cta.b64 p, [%1], %2; selp.b32 %0, 1, 0, p; }" \
        : "=r"(_done) : "r"(_mb), "r"(_par) : "memory"); \
    if (!_done) { \
        asm volatile("{ .reg .pred P1; WL_%=: mbarrier.try_wait.parity.acquire.cluster.shared::cta.b64 P1, [%0], %1, 0x989680; @P1 bra.uni WD_%=; bra.uni WL_%=; WD_%=: }" \
            :: "r"(_mb), "r"(_par) : "memory"); \
    } \
} while (0)

// =========================== prep: W transposes + emb split ================
__global__ void prep(const float* __restrict__ Wx1, const float* __restrict__ Wh1,
                     const float* __restrict__ Wx2, const float* __restrict__ Wh2,
                     const float* __restrict__ emb)
{
    __shared__ float tile[32][33];
    int blk = blockIdx.x;
    if (blk < 256) {
        int z = blk >> 6, rem = blk & 63, bx = rem & 7, by = rem >> 3;
        const float* src = (z == 0) ? Wx1 : (z == 1) ? Wh1 : (z == 2) ? Wx2 : Wh2;
        float* dst = g_WT + (size_t)z * HIDDEN * HIDDEN;
        int x0 = bx * 32, y0 = by * 32;
        int tx = threadIdx.x & 31, ty = threadIdx.x >> 5;
        for (int dy = ty; dy < 32; dy += 8)
            tile[dy][tx] = src[(y0 + dy) * HIDDEN + x0 + tx];
        __syncthreads();
        for (int dy = ty; dy < 32; dy += 8)
            dst[(x0 + dy) * HIDDEN + y0 + tx] = tile[tx][dy];
    } else {
        for (size_t i = (size_t)(blk - 256) * 256 + threadIdx.x;
             i < (size_t)VOCAB * HIDDEN; i += (size_t)8192 * 256) {
            float x = emb[i];
            __nv_bfloat16 hi = __float2bfloat16(x);
            __nv_bfloat16 lo = __float2bfloat16(x - __bfloat162float(hi));
            size_t row = i >> 8; int k = (int)(i & 255);
            __nv_bfloat16* B = g_Bext + row * KEXT;
            B[k] = hi; B[256 + k] = hi; B[512 + k] = lo;
        }
    }
}

// g_A[n,j] = bias[j] + sum_k X[n,k] * WxT[k,j]   (16 rows per CTA)
__global__ void pre_gemm(const float* __restrict__ emb, const int* __restrict__ tokens,
                         const int* __restrict__ lengths, const float* __restrict__ bias,
                         int layer)
{
    __shared__ float xs[16][HIDDEN];
    const float* WT = g_WT + (size_t)(layer == 0 ? 0 : 2) * HIDDEN * HIDDEN;
    int n0  = blockIdx.x * 16;
    int tid = threadIdx.x;

    for (int r = 0; r < 16; r++) {
        int n = n0 + r;
        float v;
        if (layer == 0) {
            int b = n / SEQ, t = n % SEQ;
            v = (t < lengths[b]) ? emb[(size_t)tokens[n] * HIDDEN + tid] : 0.f;
        } else {
            v = g_h1[(size_t)n * HIDDEN + tid];
        }
        xs[r][tid] = v;
    }
    __syncthreads();

    float acc[16];
#pragma unroll
    for (int r = 0; r < 16; r++) acc[r] = 0.f;

    for (int k = 0; k < HIDDEN; k += 8) {
        float w[8];
#pragma unroll
        for (int kk = 0; kk < 8; kk++) w[kk] = WT[(k + kk) * HIDDEN + tid];
#pragma unroll
        for (int r = 0; r < 16; r++) {
            float4 x0 = *(const float4*)&xs[r][k];
            float4 x1 = *(const float4*)&xs[r][k + 4];
            acc[r] += x0.x * w[0] + x0.y * w[1] + x0.z * w[2] + x0.w * w[3]
                    + x1.x * w[4] + x1.y * w[5] + x1.z * w[6] + x1.w * w[7];
        }
    }
    float b = bias[tid];
#pragma unroll
    for (int r = 0; r < 16; r++)
        g_A[(size_t)(n0 + r) * HIDDEN + tid] = acc[r] + b;
}

// ===== recurrence: 2-CTA cluster, W_h in regs, DOUBLE-BUFFERED hs ==========
__global__ void __cluster_dims__(2, 1, 1) __launch_bounds__(512, 1)
rnn2db(const int* __restrict__ lengths, float* __restrict__ hout, int layer)
{
    __shared__ float hs[2][HIDDEN];
    __shared__ float red[4][128];
    __shared__ alignas(8) uint64_t mbar;

    const float* WhT = g_WT + (size_t)(layer * 2 + 1) * HIDDEN * HIDDEN;
    float* out = hout ? hout : g_h1;
    bool dosplit = (hout != nullptr);

    int tid = threadIdx.x;
    int jo  = tid & 127, kq = tid >> 7, k0 = kq * 64;
    int b   = blockIdx.x >> 1;
    int r   = blockIdx.x & 1;
    int j   = r * 128 + jo;
    int len = lengths[b];

    float w[64];
#pragma unroll
    for (int kk = 0; kk < 64; kk++) w[kk] = WhT[(k0 + kk) * HIDDEN + j];

    uint32_t mb_local = smem_to_u32(&mbar);
    uint32_t hs_local = smem_to_u32(&hs[0][0]);
    uint32_t mb_peer  = mapa_u32(mb_local, r ^ 1);
    uint32_t hs_peer  = mapa_u32(hs_local, r ^ 1);

    if (tid < HIDDEN) hs[0][tid] = 0.f;
    if (tid == 0) MBARRIER_INIT(mb_local, 128);
    __syncthreads();
    CLUSTER_SYNC();

    int ph = 0;
    const float* Arow = g_A + (size_t)b * SEQ * HIDDEN + j;
    for (int t = 0; t < len; t++) {
        int rb = t & 1, wb = rb ^ 1;
        float av = 0.f;
        if (tid < 128) av = Arow[(size_t)t * HIDDEN];

        float a0 = 0.f, a1 = 0.f, a2 = 0.f, a3 = 0.f;
#pragma unroll
        for (int kk = 0; kk < 64; kk += 4) {
            float4 h4 = *(const float4*)&hs[rb][k0 + kk];
            a0 += h4.x * w[kk];
            a1 += h4.y * w[kk + 1];
            a2 += h4.z * w[kk + 2];
            a3 += h4.w * w[kk + 3];
        }
        red[kq][jo] = (a0 + a1) + (a2 + a3);
        __syncthreads();               // ALL reads of hs[rb] complete; red ready

        if (tid < 128) {
            float v = red[0][jo] + red[1][jo] + red[2][jo] + red[3][jo] + av;
            float h = tanhf(v);
            hs[wb][j] = h;
            st_cluster_f32(hs_peer + (uint32_t)(wb * HIDDEN + j) * 4u, h);
            out[((size_t)b * SEQ + t) * HIDDEN + j] = h;
            if (dosplit) {
                __nv_bfloat16 hi = __float2bfloat16(h);
                __nv_bfloat16 lo = __float2bfloat16(h - __bfloat162float(hi));
                __nv_bfloat16* A = g_Aext + ((size_t)b * SEQ + t) * KEXT;
                A[j] = hi; A[256 + j] = lo; A[512 + j] = hi;
            }
            mbar_arrive_rel_cluster(mb_peer);
        }
        __syncthreads();               // local hs[wb] visible; red reusable
        MBAR_WAIT_PARITY_CLUSTER(mb_local, ph);
        ph ^= 1;
    }
    for (int t = len; t < SEQ; t++)
        if (tid < 128) {
            out[((size_t)b * SEQ + t) * HIDDEN + j] = 0.f;
            if (dosplit) {
                __nv_bfloat16 z = __float2bfloat16(0.f);
                __nv_bfloat16* A = g_Aext + ((size_t)b * SEQ + t) * KEXT;
                A[j] = z; A[256 + j] = z; A[512 + j] = z;
            }
        }
    CLUSTER_SYNC();
}

// ==================== mma.sync projection + partial softmax ================
// R13 configuration (best measured): tile 128x128, 256 thr, 2 CTAs/SM.
// grid (250 n-tiles, 32 m-tiles), K = 768 bf16 (12 chunks of 64, double-buf).
// SMEM (69632 B): part float2[128][4] @0; A0 @4096 A1 @20480 B0 @36864 B1 @53248.
#define MMA_SMEM_BYTES 69632
__global__ void __launch_bounds__(256, 2) mma_out(float* __restrict__ probs)
{
    extern __shared__ char smem[];
    float2* part = (float2*)smem;
    uint32_t sb = smem_to_u32(smem);
    const uint32_t stA[2] = {4096u, 20480u};
    const uint32_t stB[2] = {36864u, 53248u};
    int tid = threadIdx.x, wid = tid >> 5, lane = tid & 31;
    int wm = wid >> 2, wn = wid & 3;          // warp grid 2(m) x 4(n)
    int n0 = blockIdx.x * 128, m0 = blockIdx.y * 128;

    const char* Agm = (const char*)g_Aext;    // row stride 1536 B
    const char* Bgm = (const char*)g_Bext;

    float c[4][4][4];
#pragma unroll
    for (int i = 0; i < 4; i++)
#pragma unroll
        for (int jx = 0; jx < 4; jx++)
#pragma unroll
            for (int q = 0; q < 4; q++) c[i][jx][q] = 0.f;

#define STAGE_COPY(s, buf) do {                                                    \
        int _kb = (s) * 128;                                                       \
        _Pragma("unroll")                                                          \
        for (int _i = 0; _i < 4; _i++) {                                           \
            int _idx = tid + _i * 256;                                             \
            int _row = _idx >> 3, _g = _idx & 7;                                   \
            uint32_t _sw = SMEM_SWIZZLE_128B((uint32_t)(_row * 128 + _g * 16));    \
            cp_async16(sb + stA[buf] + _sw,                                        \
                       Agm + (size_t)(m0 + _row) * 1536 + _kb + _g * 16);          \
            cp_async16(sb + stB[buf] + _sw,                                        \
                       Bgm + (size_t)(n0 + _row) * 1536 + _kb + _g * 16);          \
        }                                                                          \
    } while (0)

    STAGE_COPY(0, 0);
    CP_COMMIT(); CP_WAIT0();
    __syncthreads();

    for (int s = 0; s < 12; s++) {
        int buf = s & 1;
        if (s < 11) { STAGE_COPY(s + 1, buf ^ 1); CP_COMMIT(); }
        uint32_t abase = sb + stA[buf], bbase = sb + stB[buf];
        int sub = lane >> 3;
#pragma unroll
        for (int kk = 0; kk < 4; kk++) {
            uint32_t a[4][4];
#pragma unroll
            for (int mi = 0; mi < 4; mi++) {
                int row = wm * 64 + mi * 16 + (lane & 7) + (sub & 1) * 8;
                int kb  = kk * 32 + (sub >> 1) * 16;
                ldm_x4(a[mi][0], a[mi][1], a[mi][2], a[mi][3],
                       abase + SMEM_SWIZZLE_128B((uint32_t)(row * 128 + kb)));
            }
#pragma unroll
            for (int np = 0; np < 2; np++) {
                uint32_t b0, b1, b2, b3;
                int nrow = wn * 32 + np * 16 + (lane & 7) + (sub >> 1) * 8;
                int kb   = kk * 32 + (sub & 1) * 16;
                ldm_x4(b0, b1, b2, b3,
                       bbase + SMEM_SWIZZLE_128B((uint32_t)(nrow * 128 + kb)));
#pragma unroll
                for (int mi = 0; mi < 4; mi++) {
                    mma16816(c[mi][np * 2],     a[mi], b0, b1);
                    mma16816(c[mi][np * 2 + 1], a[mi], b2, b3);
                }
            }
        }
        if (s < 11) CP_WAIT0();
        __syncthreads();
    }

    int gq = lane >> 2, tq = lane & 3;
#pragma unroll
    for (int mi = 0; mi < 4; mi++) {
#pragma unroll
        for (int h = 0; h < 2; h++) {
            int rloc = wm * 64 + mi * 16 + gq + h * 8;
            size_t grow = (size_t)(m0 + rloc);
            float m = -1e30f, ssum = 0.f;
#pragma unroll
            for (int ni = 0; ni < 4; ni++) {
                float v0 = c[mi][ni][2 * h], v1 = c[mi][ni][2 * h + 1];
                int col = n0 + wn * 32 + ni * 8 + 2 * tq;
                *(float2*)&probs[grow * VOCAB + col] = make_float2(v0, v1);
                float mn = fmaxf(m, fmaxf(v0, v1));
                ssum = ssum * __expf(m - mn) + __expf(v0 - mn) + __expf(v1 - mn);
                m = mn;
            }
#pragma unroll
            for (int o = 1; o <= 2; o <<= 1) {
                float mo = __shfl_xor_sync(0xffffffffu, m, o);
                float so = __shfl_xor_sync(0xffffffffu, ssum, o);
                float mn = fmaxf(m, mo);
                ssum = ssum * __expf(m - mn) + so * __expf(mo - mn);
                m = mn;
            }
            if (tq == 0) part[rloc * 4 + wn] = make_float2(m, ssum);
        }
    }
    __syncthreads();
    if (tid < 128) {
        float2 p0 = part[tid * 4 + 0], p1 = part[tid * 4 + 1];
        float2 p2 = part[tid * 4 + 2], p3 = part[tid * 4 + 3];
        float M = fmaxf(fmaxf(p0.x, p1.x), fmaxf(p2.x, p3.x));
        float S = p0.y * __expf(p0.x - M) + p1.y * __expf(p1.x - M)
                + p2.y * __expf(p2.x - M) + p3.y * __expf(p3.x - M);
        g_pmax[(size_t)(m0 + tid) * 256 + blockIdx.x] = M;
        g_psum[(size_t)(m0 + tid) * 256 + blockIdx.x] = S;
    }
}

// ========== fused combine + normalize: one block per row ==================
__global__ void __launch_bounds__(256) normalize_probs(const int* __restrict__ lengths,
                                                       float* __restrict__ probs)
{
    __shared__ float wM[8], wS[8];
    __shared__ float rowM, rowInv;
    int row  = blockIdx.x;
    int tid  = threadIdx.x;
    int lane = tid & 31, wrp = tid >> 5;

    // reduce 250 per-tile partials for this row
    const float* pm = &g_pmax[(size_t)row * 256];
    const float* ps = &g_psum[(size_t)row * 256];
    float M = -1e30f, S = 0.f;
    for (int i = tid; i < NTILES; i += 256) {
        float m = pm[i], s = ps[i];
        float mn = fmaxf(M, m);
        S = S * __expf(M - mn) + s * __expf(m - mn);
        M = mn;
    }
    for (int o = 16; o; o >>= 1) {
        float mo = __shfl_xor_sync(0xffffffffu, M, o);
        float so = __shfl_xor_sync(0xffffffffu, S, o);
        float mn = fmaxf(M, mo);
        S = S * __expf(M - mn) + so * __expf(mo - mn);
        M = mn;
    }
    if (lane == 0) { wM[wrp] = M; wS[wrp] = S; }
    __syncthreads();
    if (tid == 0) {
        float M2 = -1e30f, S2 = 0.f;
#pragma unroll
        for (int i = 0; i < 8; i++) {
            float mn = fmaxf(M2, wM[i]);
            S2 = S2 * __expf(M2 - mn) + wS[i] * __expf(wM[i] - mn);
            M2 = mn;
        }
        int b = row >> 7, t = row & 127;
        rowM   = M2;
        rowInv = (t < lengths[b]) ? (1.f / S2) : 0.f;
    }
    __syncthreads();

    float Mv = rowM, inv = rowInv;
    float4* p = (float4*)(probs + (size_t)row * VOCAB);
    for (int i = tid; i < VOCAB / 4; i += 256) {
        float4 v = p[i];
        v.x = __expf(v.x - Mv) * inv;
        v.y = __expf(v.y - Mv) * inv;
        v.z = __expf(v.z - Mv) * inv;
        v.w = __expf(v.w - Mv) * inv;
        p[i] = v;
    }
}

// ---------------------------------------------------------------------------
extern "C" void kernel_launch(void* const* d_in, const int* in_sizes, int n_in,
                              void* d_out, int out_size)
{
    const int*   tokens  = (const int*)  d_in[0];
    const int*   lengths = (const int*)  d_in[1];
    const float* emb     = (const float*)d_in[2];
    const float* Wx1 = (const float*)d_in[3];
    const float* Wh1 = (const float*)d_in[4];
    const float* b1  = (const float*)d_in[5];
    const float* Wx2 = (const float*)d_in[6];
    const float* Wh2 = (const float*)d_in[7];
    const float* b2  = (const float*)d_in[8];

    float* probs = (float*)d_out;
    float* h2    = probs + PROBS_ELEMS;

    cudaFuncSetAttribute(mma_out, cudaFuncAttributeMaxDynamicSharedMemorySize,
                         MMA_SMEM_BYTES);

    prep    <<<8448, 256>>>(Wx1, Wh1, Wx2, Wh2, emb);
    pre_gemm<<<NPOS / 16, 256>>>(emb, tokens, lengths, b1, 0);
    rnn2db  <<<2 * BATCH, 512>>>(lengths, nullptr, 0);
    pre_gemm<<<NPOS / 16, 256>>>(emb, tokens, lengths, b2, 1);
    rnn2db  <<<2 * BATCH, 512>>>(lengths, h2, 1);                 // + bf16 split
    mma_out <<<dim3(NTILES, MTILES), 256, MMA_SMEM_BYTES>>>(probs);
    normalize_probs<<<NPOS, 256>>>(lengths, probs);
}

// round 17
// speedup vs baseline: 1.5577x; 1.4512x over previous
#include <cuda_runtime.h>
#include <cuda_bf16.h>
#include <cstdint>
#include <math.h>

#define VOCAB  32000
#define HIDDEN 256
#define BATCH  32
#define SEQ    128
#define NPOS   (BATCH * SEQ)                  // 4096
#define PROBS_ELEMS ((size_t)NPOS * VOCAB)    // 131,072,000
#define KEXT   768                            // [h_hi | h_lo | h_hi] x [e_hi | e_hi | e_lo]
#define NTILES (VOCAB / 128)                  // 250
#define MTILES (NPOS / 128)                   // 32

// ---- device scratch ----
__device__ float g_A[NPOS * HIDDEN];
__device__ float g_h1[NPOS * HIDDEN];
__device__ float g_WT[4 * HIDDEN * HIDDEN];
__device__ __nv_bfloat16 g_Aext[(size_t)NPOS * KEXT];    // 6 MB; tail beyond valid stays 0
__device__ __nv_bfloat16 g_Bext[(size_t)VOCAB * KEXT];   // 49 MB
__device__ float g_pmax[(size_t)NPOS * 256];             // [orig_row][ntile]
__device__ float g_psum[(size_t)NPOS * 256];
__device__ int   g_rowmap[NPOS];                         // compacted -> original row
__device__ int   g_valid;                                // sum(lengths)

// =========================== PTX helpers (sm_90 baseline) ==================
__device__ __forceinline__ uint32_t smem_to_u32(const void* p) {
    uint32_t a;
    asm("{ .reg .u64 t; cvta.to.shared.u64 t, %1; cvt.u32.u64 %0, t; }" : "=r"(a) : "l"(p));
    return a;
}
#define SMEM_SWIZZLE_128B(off) ((off) ^ (((off) >> 3) & 0x70))

__device__ __forceinline__ void cp_async16(uint32_t dst, const void* src) {
    asm volatile("cp.async.cg.shared.global [%0], [%1], 16;" :: "r"(dst), "l"(src) : "memory");
}
#define CP_COMMIT() asm volatile("cp.async.commit_group;" ::: "memory")
#define CP_WAIT0()  asm volatile("cp.async.wait_group 0;" ::: "memory")

__device__ __forceinline__ void ldm_x4(uint32_t& r0, uint32_t& r1, uint32_t& r2, uint32_t& r3,
                                       uint32_t addr) {
    asm volatile("ldmatrix.sync.aligned.m8n8.x4.shared.b16 {%0,%1,%2,%3}, [%4];"
                 : "=r"(r0), "=r"(r1), "=r"(r2), "=r"(r3) : "r"(addr));
}
__device__ __forceinline__ void mma16816(float* c, const uint32_t* a, uint32_t b0, uint32_t b1) {
    asm volatile("mma.sync.aligned.m16n8k16.row.col.f32.bf16.bf16.f32 "
                 "{%0,%1,%2,%3}, {%4,%5,%6,%7}, {%8,%9}, {%0,%1,%2,%3};"
                 : "+f"(c[0]), "+f"(c[1]), "+f"(c[2]), "+f"(c[3])
                 : "r"(a[0]), "r"(a[1]), "r"(a[2]), "r"(a[3]), "r"(b0), "r"(b1));
}

// cluster helpers
__device__ __forceinline__ uint32_t mapa_u32(uint32_t addr, uint32_t rank) {
    uint32_t r;
    asm("mapa.shared::cluster.u32 %0, %1, %2;" : "=r"(r) : "r"(addr), "r"(rank));
    return r;
}
__device__ __forceinline__ void st_cluster_f32(uint32_t addr, float v) {
    asm volatile("st.shared::cluster.f32 [%0], %1;" :: "r"(addr), "f"(v) : "memory");
}
__device__ __forceinline__ void mbar_arrive_rel_cluster(uint32_t remote_mb) {
    asm volatile("mbarrier.arrive.release.cluster.shared::cluster.b64 _, [%0];"
                 :: "r"(remote_mb) : "memory");
}
#define MBARRIER_INIT(mb, cnt) \
    asm volatile("mbarrier.init.shared.b64 [%0], %1;" :: "r"((uint32_t)(mb)), "r"((uint32_t)(cnt)) : "memory")
#define CLUSTER_SYNC() do { \
    asm volatile("barrier.cluster.arrive.aligned;" ::: "memory"); \
    asm volatile("barrier.cluster.wait.aligned;" ::: "memory"); \
} while (0)
#define MBAR_WAIT_PARITY_CLUSTER(mb, par) do { \
    uint32_t _mb = (mb), _par = (par), _done; \
    asm volatile("{ .reg .pred p; mbarrier.try_wait.parity.acquire.cluster.shared::cta.b64 p, [%1], %2; selp.b32 %0, 1, 0, p; }" \
        : "=r"(_done) : "r"(_mb), "r"(_par) : "memory"); \
    if (!_done) { \
        asm volatile("{ .reg .pred P1; WL_%=: mbarrier.try_wait.parity.acquire.cluster.shared::cta.b64 P1, [%0], %1, 0x989680; @P1 bra.uni WD_%=; bra.uni WL_%=; WD_%=: }" \
            :: "r"(_mb), "r"(_par) : "memory"); \
    } \
} while (0)

// =========================== prep: W transposes + emb split + valid count ==
__global__ void prep(const float* __restrict__ Wx1, const float* __restrict__ Wh1,
                     const float* __restrict__ Wx2, const float* __restrict__ Wh2,
                     const float* __restrict__ emb, const int* __restrict__ lengths)
{
    __shared__ float tile[32][33];
    int blk = blockIdx.x;
    if (blk == 0 && threadIdx.x == 0) {
        int v = 0;
        for (int i = 0; i < BATCH; i++) v += lengths[i];
        g_valid = v;
    }
    if (blk < 256) {
        int z = blk >> 6, rem = blk & 63, bx = rem & 7, by = rem >> 3;
        const float* src = (z == 0) ? Wx1 : (z == 1) ? Wh1 : (z == 2) ? Wx2 : Wh2;
        float* dst = g_WT + (size_t)z * HIDDEN * HIDDEN;
        int x0 = bx * 32, y0 = by * 32;
        int tx = threadIdx.x & 31, ty = threadIdx.x >> 5;
        for (int dy = ty; dy < 32; dy += 8)
            tile[dy][tx] = src[(y0 + dy) * HIDDEN + x0 + tx];
        __syncthreads();
        for (int dy = ty; dy < 32; dy += 8)
            dst[(x0 + dy) * HIDDEN + y0 + tx] = tile[tx][dy];
    } else {
        for (size_t i = (size_t)(blk - 256) * 256 + threadIdx.x;
             i < (size_t)VOCAB * HIDDEN; i += (size_t)8192 * 256) {
            float x = emb[i];
            __nv_bfloat16 hi = __float2bfloat16(x);
            __nv_bfloat16 lo = __float2bfloat16(x - __bfloat162float(hi));
            size_t row = i >> 8; int k = (int)(i & 255);
            __nv_bfloat16* B = g_Bext + row * KEXT;
            B[k] = hi; B[256 + k] = hi; B[512 + k] = lo;
        }
    }
}

// g_A[n,j] = bias[j] + sum_k X[n,k] * WxT[k,j]   (16 rows per CTA)
__global__ void pre_gemm(const float* __restrict__ emb, const int* __restrict__ tokens,
                         const int* __restrict__ lengths, const float* __restrict__ bias,
                         int layer)
{
    __shared__ float xs[16][HIDDEN];
    const float* WT = g_WT + (size_t)(layer == 0 ? 0 : 2) * HIDDEN * HIDDEN;
    int n0  = blockIdx.x * 16;
    int tid = threadIdx.x;

    for (int r = 0; r < 16; r++) {
        int n = n0 + r;
        float v;
        if (layer == 0) {
            int b = n / SEQ, t = n % SEQ;
            v = (t < lengths[b]) ? emb[(size_t)tokens[n] * HIDDEN + tid] : 0.f;
        } else {
            v = g_h1[(size_t)n * HIDDEN + tid];
        }
        xs[r][tid] = v;
    }
    __syncthreads();

    float acc[16];
#pragma unroll
    for (int r = 0; r < 16; r++) acc[r] = 0.f;

    for (int k = 0; k < HIDDEN; k += 8) {
        float w[8];
#pragma unroll
        for (int kk = 0; kk < 8; kk++) w[kk] = WT[(k + kk) * HIDDEN + tid];
#pragma unroll
        for (int r = 0; r < 16; r++) {
            float4 x0 = *(const float4*)&xs[r][k];
            float4 x1 = *(const float4*)&xs[r][k + 4];
            acc[r] += x0.x * w[0] + x0.y * w[1] + x0.z * w[2] + x0.w * w[3]
                    + x1.x * w[4] + x1.y * w[5] + x1.z * w[6] + x1.w * w[7];
        }
    }
    float b = bias[tid];
#pragma unroll
    for (int r = 0; r < 16; r++)
        g_A[(size_t)(n0 + r) * HIDDEN + tid] = acc[r] + b;
}

// ===== recurrence: 2-CTA cluster, W_h in regs, DOUBLE-BUFFERED hs ==========
// Layer 2 (dosplit): bf16 split rows written COMPACTED at off[b]+t; rowmap
// records original row. Tail of g_Aext is never written (stays zero-init).
__global__ void __cluster_dims__(2, 1, 1) __launch_bounds__(512, 1)
rnn2db(const int* __restrict__ lengths, float* __restrict__ hout, int layer)
{
    __shared__ float hs[2][HIDDEN];
    __shared__ float red[4][128];
    __shared__ alignas(8) uint64_t mbar;
    __shared__ int s_off;

    const float* WhT = g_WT + (size_t)(layer * 2 + 1) * HIDDEN * HIDDEN;
    float* out = hout ? hout : g_h1;
    bool dosplit = (hout != nullptr);

    int tid = threadIdx.x;
    int jo  = tid & 127, kq = tid >> 7, k0 = kq * 64;
    int b   = blockIdx.x >> 1;
    int r   = blockIdx.x & 1;
    int j   = r * 128 + jo;
    int len = lengths[b];

    float w[64];
#pragma unroll
    for (int kk = 0; kk < 64; kk++) w[kk] = WhT[(k0 + kk) * HIDDEN + j];

    uint32_t mb_local = smem_to_u32(&mbar);
    uint32_t hs_local = smem_to_u32(&hs[0][0]);
    uint32_t mb_peer  = mapa_u32(mb_local, r ^ 1);
    uint32_t hs_peer  = mapa_u32(hs_local, r ^ 1);

    if (tid < HIDDEN) hs[0][tid] = 0.f;
    if (tid == 0) {
        MBARRIER_INIT(mb_local, 128);
        int o = 0;
        for (int i = 0; i < b; i++) o += lengths[i];
        s_off = o;
    }
    __syncthreads();
    CLUSTER_SYNC();

    int off = s_off;
    int ph = 0;
    const float* Arow = g_A + (size_t)b * SEQ * HIDDEN + j;
    for (int t = 0; t < len; t++) {
        int rb = t & 1, wb = rb ^ 1;
        float av = 0.f;
        if (tid < 128) av = Arow[(size_t)t * HIDDEN];

        float a0 = 0.f, a1 = 0.f, a2 = 0.f, a3 = 0.f;
#pragma unroll
        for (int kk = 0; kk < 64; kk += 4) {
            float4 h4 = *(const float4*)&hs[rb][k0 + kk];
            a0 += h4.x * w[kk];
            a1 += h4.y * w[kk + 1];
            a2 += h4.z * w[kk + 2];
            a3 += h4.w * w[kk + 3];
        }
        red[kq][jo] = (a0 + a1) + (a2 + a3);
        __syncthreads();               // ALL reads of hs[rb] complete; red ready

        if (tid < 128) {
            float v = red[0][jo] + red[1][jo] + red[2][jo] + red[3][jo] + av;
            float h = tanhf(v);
            hs[wb][j] = h;
            st_cluster_f32(hs_peer + (uint32_t)(wb * HIDDEN + j) * 4u, h);
            out[((size_t)b * SEQ + t) * HIDDEN + j] = h;
            if (dosplit) {
                int crow = off + t;
                __nv_bfloat16 hi = __float2bfloat16(h);
                __nv_bfloat16 lo = __float2bfloat16(h - __bfloat162float(hi));
                __nv_bfloat16* A = g_Aext + (size_t)crow * KEXT;
                A[j] = hi; A[256 + j] = lo; A[512 + j] = hi;
                if (tid == 0 && r == 0) g_rowmap[crow] = b * SEQ + t;
            }
            mbar_arrive_rel_cluster(mb_peer);
        }
        __syncthreads();               // local hs[wb] visible; red reusable
        MBAR_WAIT_PARITY_CLUSTER(mb_local, ph);
        ph ^= 1;
    }
    for (int t = len; t < SEQ; t++)
        if (tid < 128)
            out[((size_t)b * SEQ + t) * HIDDEN + j] = 0.f;   // h2/h1 zeros only
    CLUSTER_SYNC();
}

// ==================== mma.sync projection + partial softmax ================
// R13 config (128x128, 2 CTAs/SM) over COMPACTED rows; m-tiles beyond
// g_valid exit immediately. Epilogue scatters to original rows via g_rowmap.
#define MMA_SMEM_BYTES 69632
__global__ void __launch_bounds__(256, 2) mma_out(float* __restrict__ probs)
{
    extern __shared__ char smem[];
    float2* part = (float2*)smem;
    uint32_t sb = smem_to_u32(smem);
    const uint32_t stA[2] = {4096u, 20480u};
    const uint32_t stB[2] = {36864u, 53248u};
    int tid = threadIdx.x, wid = tid >> 5, lane = tid & 31;
    int wm = wid >> 2, wn = wid & 3;          // warp grid 2(m) x 4(n)
    int n0 = blockIdx.x * 128, m0 = blockIdx.y * 128;

    int valid = g_valid;
    if (m0 >= valid) return;

    const char* Agm = (const char*)g_Aext;    // row stride 1536 B
    const char* Bgm = (const char*)g_Bext;

    float c[4][4][4];
#pragma unroll
    for (int i = 0; i < 4; i++)
#pragma unroll
        for (int jx = 0; jx < 4; jx++)
#pragma unroll
            for (int q = 0; q < 4; q++) c[i][jx][q] = 0.f;

#define STAGE_COPY(s, buf) do {                                                    \
        int _kb = (s) * 128;                                                       \
        _Pragma("unroll")                                                          \
        for (int _i = 0; _i < 4; _i++) {                                           \
            int _idx = tid + _i * 256;                                             \
            int _row = _idx >> 3, _g = _idx & 7;                                   \
            uint32_t _sw = SMEM_SWIZZLE_128B((uint32_t)(_row * 128 + _g * 16));    \
            cp_async16(sb + stA[buf] + _sw,                                        \
                       Agm + (size_t)(m0 + _row) * 1536 + _kb + _g * 16);          \
            cp_async16(sb + stB[buf] + _sw,                                        \
                       Bgm + (size_t)(n0 + _row) * 1536 + _kb + _g * 16);          \
        }                                                                          \
    } while (0)

    STAGE_COPY(0, 0);
    CP_COMMIT(); CP_WAIT0();
    __syncthreads();

    for (int s = 0; s < 12; s++) {
        int buf = s & 1;
        if (s < 11) { STAGE_COPY(s + 1, buf ^ 1); CP_COMMIT(); }
        uint32_t abase = sb + stA[buf], bbase = sb + stB[buf];
        int sub = lane >> 3;
#pragma unroll
        for (int kk = 0; kk < 4; kk++) {
            uint32_t a[4][4];
#pragma unroll
            for (int mi = 0; mi < 4; mi++) {
                int row = wm * 64 + mi * 16 + (lane & 7) + (sub & 1) * 8;
                int kb  = kk * 32 + (sub >> 1) * 16;
                ldm_x4(a[mi][0], a[mi][1], a[mi][2], a[mi][3],
                       abase + SMEM_SWIZZLE_128B((uint32_t)(row * 128 + kb)));
            }
#pragma unroll
            for (int np = 0; np < 2; np++) {
                uint32_t b0, b1, b2, b3;
                int nrow = wn * 32 + np * 16 + (lane & 7) + (sub >> 1) * 8;
                int kb   = kk * 32 + (sub & 1) * 16;
                ldm_x4(b0, b1, b2, b3,
                       bbase + SMEM_SWIZZLE_128B((uint32_t)(nrow * 128 + kb)));
#pragma unroll
                for (int mi = 0; mi < 4; mi++) {
                    mma16816(c[mi][np * 2],     a[mi], b0, b1);
                    mma16816(c[mi][np * 2 + 1], a[mi], b2, b3);
                }
            }
        }
        if (s < 11) CP_WAIT0();
        __syncthreads();
    }

    int gq = lane >> 2, tq = lane & 3;
#pragma unroll
    for (int mi = 0; mi < 4; mi++) {
#pragma unroll
        for (int h = 0; h < 2; h++) {
            int rloc = wm * 64 + mi * 16 + gq + h * 8;
            int cm   = m0 + rloc;
            bool act = (cm < valid);
            size_t orow = act ? (size_t)g_rowmap[cm] : 0;
            float m = -1e30f, ssum = 0.f;
#pragma unroll
            for (int ni = 0; ni < 4; ni++) {
                float v0 = c[mi][ni][2 * h], v1 = c[mi][ni][2 * h + 1];
                int col = n0 + wn * 32 + ni * 8 + 2 * tq;
                if (act)
                    *(float2*)&probs[orow * VOCAB + col] = make_float2(v0, v1);
                float mn = fmaxf(m, fmaxf(v0, v1));
                ssum = ssum * __expf(m - mn) + __expf(v0 - mn) + __expf(v1 - mn);
                m = mn;
            }
#pragma unroll
            for (int o = 1; o <= 2; o <<= 1) {
                float mo = __shfl_xor_sync(0xffffffffu, m, o);
                float so = __shfl_xor_sync(0xffffffffu, ssum, o);
                float mn = fmaxf(m, mo);
                ssum = ssum * __expf(m - mn) + so * __expf(mo - mn);
                m = mn;
            }
            if (tq == 0 && act) part[rloc * 4 + wn] = make_float2(m, ssum);
        }
    }
    __syncthreads();
    if (tid < 128 && m0 + tid < valid) {
        float2 p0 = part[tid * 4 + 0], p1 = part[tid * 4 + 1];
        float2 p2 = part[tid * 4 + 2], p3 = part[tid * 4 + 3];
        float M = fmaxf(fmaxf(p0.x, p1.x), fmaxf(p2.x, p3.x));
        float S = p0.y * __expf(p0.x - M) + p1.y * __expf(p1.x - M)
                + p2.y * __expf(p2.x - M) + p3.y * __expf(p3.x - M);
        size_t orow = (size_t)g_rowmap[m0 + tid];
        g_pmax[orow * 256 + blockIdx.x] = M;
        g_psum[orow * 256 + blockIdx.x] = S;
    }
}

// ========== fused combine + normalize; masked rows -> pure zero-write ======
__global__ void __launch_bounds__(256) normalize_probs(const int* __restrict__ lengths,
                                                       float* __restrict__ probs)
{
    __shared__ float wM[8], wS[8];
    __shared__ float rowM, rowInv;
    int row  = blockIdx.x;
    int tid  = threadIdx.x;
    int lane = tid & 31, wrp = tid >> 5;
    int b = row >> 7, t = row & 127;

    if (t >= lengths[b]) {              // masked: write zeros, no reads
        float4 z = make_float4(0.f, 0.f, 0.f, 0.f);
        float4* p = (float4*)(probs + (size_t)row * VOCAB);
        for (int i = tid; i < VOCAB / 4; i += 256) p[i] = z;
        return;
    }

    const float* pm = &g_pmax[(size_t)row * 256];
    const float* ps = &g_psum[(size_t)row * 256];
    float M = -1e30f, S = 0.f;
    for (int i = tid; i < NTILES; i += 256) {
        float m = pm[i], s = ps[i];
        float mn = fmaxf(M, m);
        S = S * __expf(M - mn) + s * __expf(m - mn);
        M = mn;
    }
    for (int o = 16; o; o >>= 1) {
        float mo = __shfl_xor_sync(0xffffffffu, M, o);
        float so = __shfl_xor_sync(0xffffffffu, S, o);
        float mn = fmaxf(M, mo);
        S = S * __expf(M - mn) + so * __expf(mo - mn);
        M = mn;
    }
    if (lane == 0) { wM[wrp] = M; wS[wrp] = S; }
    __syncthreads();
    if (tid == 0) {
        float M2 = -1e30f, S2 = 0.f;
#pragma unroll
        for (int i = 0; i < 8; i++) {
            float mn = fmaxf(M2, wM[i]);
            S2 = S2 * __expf(M2 - mn) + wS[i] * __expf(wM[i] - mn);
            M2 = mn;
        }
        rowM   = M2;
        rowInv = 1.f / S2;
    }
    __syncthreads();

    float Mv = rowM, inv = rowInv;
    float4* p = (float4*)(probs + (size_t)row * VOCAB);
    for (int i = tid; i < VOCAB / 4; i += 256) {
        float4 v = p[i];
        v.x = __expf(v.x - Mv) * inv;
        v.y = __expf(v.y - Mv) * inv;
        v.z = __expf(v.z - Mv) * inv;
        v.w = __expf(v.w - Mv) * inv;
        p[i] = v;
    }
}

// ---------------------------------------------------------------------------
extern "C" void kernel_launch(void* const* d_in, const int* in_sizes, int n_in,
                              void* d_out, int out_size)
{
    const int*   tokens  = (const int*)  d_in[0];
    const int*   lengths = (const int*)  d_in[1];
    const float* emb     = (const float*)d_in[2];
    const float* Wx1 = (const float*)d_in[3];
    const float* Wh1 = (const float*)d_in[4];
    const float* b1  = (const float*)d_in[5];
    const float* Wx2 = (const float*)d_in[6];
    const float* Wh2 = (const float*)d_in[7];
    const float* b2  = (const float*)d_in[8];

    float* probs = (float*)d_out;
    float* h2    = probs + PROBS_ELEMS;

    cudaFuncSetAttribute(mma_out, cudaFuncAttributeMaxDynamicSharedMemorySize,
                         MMA_SMEM_BYTES);

    prep    <<<8448, 256>>>(Wx1, Wh1, Wx2, Wh2, emb, lengths);
    pre_gemm<<<NPOS / 16, 256>>>(emb, tokens, lengths, b1, 0);
    rnn2db  <<<2 * BATCH, 512>>>(lengths, nullptr, 0);
    pre_gemm<<<NPOS / 16, 256>>>(emb, tokens, lengths, b2, 1);
    rnn2db  <<<2 * BATCH, 512>>>(lengths, h2, 1);                 // compacted split
    mma_out <<<dim3(NTILES, MTILES), 256, MMA_SMEM_BYTES>>>(probs);
    normalize_probs<<<NPOS, 256>>>(lengths, probs);
}